// round 11
// baseline (speedup 1.0000x reference)
#include <cuda_runtime.h>
#include <math.h>

#define NNODES 100000
#define NEDGES 3200000
#define HD 64
#define DINP 15
#define DOUT 12
#define NTYPE 5
#define NGRAPH 256
#define NSTEPS 6

#define SCAN_B 1024
#define NB ((NNODES + SCAN_B - 1) / SCAN_B)   // 98

// ---------------- scratch (device globals; no allocation) ----------------
__device__ float g_out0[NNODES * HD];
__device__ float g_h[NNODES * HD];
__device__ float g_m[NNODES * HD];
__device__ float g_i1[NNODES * HD];
__device__ float g_j1[NNODES * HD];
__device__ float g_gx[(size_t)NNODES * 192];
__device__ float g_deginv[NNODES];
__device__ int   g_rowptr[NNODES + 1];
__device__ int   g_cnt[NNODES];
__device__ int   g_cursor[NNODES];
__device__ int   g_bsums[128];
__device__ int   g_ecsr[NEDGES];

// ---------------- CSR build ----------------
__global__ void zero_cnt_kernel() {
    int i = blockIdx.x * blockDim.x + threadIdx.x;
    if (i < NNODES) g_cnt[i] = 0;
}

__global__ void hist_kernel(const int* __restrict__ dst) {
    int e = blockIdx.x * blockDim.x + threadIdx.x;
    if (e < NEDGES) atomicAdd(&g_cnt[dst[e]], 1);
}

__global__ void scan1_kernel() {
    __shared__ int s[SCAN_B];
    int tid = threadIdx.x;
    int g = blockIdx.x * SCAN_B + tid;
    int v = (g < NNODES) ? g_cnt[g] : 0;
    s[tid] = v;
    __syncthreads();
    for (int off = 1; off < SCAN_B; off <<= 1) {
        int t = (tid >= off) ? s[tid - off] : 0;
        __syncthreads();
        s[tid] += t;
        __syncthreads();
    }
    if (g < NNODES) g_rowptr[g] = s[tid] - v;
    if (tid == SCAN_B - 1) g_bsums[blockIdx.x] = s[tid];
}

__global__ void scan2_kernel() {
    __shared__ int s[128];
    int tid = threadIdx.x;
    int v = (tid < NB) ? g_bsums[tid] : 0;
    s[tid] = v;
    __syncthreads();
    for (int off = 1; off < 128; off <<= 1) {
        int t = (tid >= off) ? s[tid - off] : 0;
        __syncthreads();
        s[tid] += t;
        __syncthreads();
    }
    if (tid < NB) g_bsums[tid] = s[tid] - v;
    if (tid == 127) g_rowptr[NNODES] = s[127];
}

__global__ void scan3_kernel() {
    int g = blockIdx.x * blockDim.x + threadIdx.x;
    if (g >= NNODES) return;
    g_rowptr[g] += g_bsums[g >> 10];
    g_cursor[g] = 0;
    int d = g_cnt[g];
    g_deginv[g] = 1.0f / (float)(d > 0 ? d : 1);
}

__global__ void scatter_kernel(const int* __restrict__ src,
                               const int* __restrict__ dst,
                               const int* __restrict__ typ) {
    int e = blockIdx.x * blockDim.x + threadIdx.x;
    if (e >= NEDGES) return;
    int d = dst[e];
    int pos = atomicAdd(&g_cursor[d], 1);
    g_ecsr[g_rowptr[d] + pos] = src[e] | (typ[e] << 17);  // N < 2^17
}

// ---------------- tf32 mma helper ----------------
__device__ __forceinline__ void mma_tf32(float* d, const unsigned* a, const unsigned* b) {
    asm volatile(
        "mma.sync.aligned.m16n8k8.row.col.f32.tf32.tf32.f32 "
        "{%0,%1,%2,%3}, {%4,%5,%6,%7}, {%8,%9}, {%0,%1,%2,%3};\n"
        : "+f"(d[0]), "+f"(d[1]), "+f"(d[2]), "+f"(d[3])
        : "r"(a[0]), "r"(a[1]), "r"(a[2]), "r"(a[3]), "r"(b[0]), "r"(b[1]));
}

// ============================================================================
// Fused NNConv: gather+aggregate per-type neighbor sums into smem A-tile
// (128 x 320), then tf32 GEMM vs edge_embed [320,64].
// m = relu((Agg @ W_stack) * deginv + conv_bias)
// dynamic smem: As[128*324] + Bs[32*72]  (~175 KB)
// ============================================================================
__global__ void __launch_bounds__(256)
nnconv_kernel(const float2* __restrict__ h2, const float* __restrict__ B,
              const float* __restrict__ bias, const float* __restrict__ deginv,
              float* __restrict__ Mout, int nrows) {
    extern __shared__ float smem[];
    float* As = smem;                 // [128][324]
    float* Bs = smem + 128 * 324;     // [32][72]
    const int tid = threadIdx.x;
    const int lane = tid & 31;
    const int wid = tid >> 5;
    const int warpRow = wid >> 1;
    const int warpCol = wid & 1;
    const int g = lane >> 2;
    const int tig = lane & 3;
    const int rowBlk = blockIdx.x * 128;

    // ---- gather phase: warp wid handles rows wid*16 .. wid*16+15 ----
    for (int i = 0; i < 16; i++) {
        int r = wid * 16 + i;
        int n = rowBlk + r;
        float2 acc[NTYPE];
#pragma unroll
        for (int t = 0; t < NTYPE; t++) { acc[t].x = 0.f; acc[t].y = 0.f; }
        if (n < nrows) {
            int s = g_rowptr[n];
            int e = g_rowptr[n + 1];
            int ii = s;
            for (; ii + 1 < e; ii += 2) {
                int e0 = __ldg(&g_ecsr[ii]);
                int e1 = __ldg(&g_ecsr[ii + 1]);
                float2 v0 = h2[(e0 & 0x1FFFF) * 32 + lane];
                float2 v1 = h2[(e1 & 0x1FFFF) * 32 + lane];
                int t0 = e0 >> 17, t1 = e1 >> 17;
#pragma unroll
                for (int t = 0; t < NTYPE; t++) {
                    if (t0 == t) { acc[t].x += v0.x; acc[t].y += v0.y; }
                    if (t1 == t) { acc[t].x += v1.x; acc[t].y += v1.y; }
                }
            }
            if (ii < e) {
                int e0 = __ldg(&g_ecsr[ii]);
                float2 v0 = h2[(e0 & 0x1FFFF) * 32 + lane];
                int t0 = e0 >> 17;
#pragma unroll
                for (int t = 0; t < NTYPE; t++)
                    if (t0 == t) { acc[t].x += v0.x; acc[t].y += v0.y; }
            }
        }
#pragma unroll
        for (int t = 0; t < NTYPE; t++)
            *reinterpret_cast<float2*>(&As[r * 324 + t * 64 + lane * 2]) = acc[t];
    }

    // ---- GEMM phase: K=320, M=64 ----
    float acc[2][4][4];
#pragma unroll
    for (int mt = 0; mt < 2; mt++)
#pragma unroll
        for (int nt = 0; nt < 4; nt++)
#pragma unroll
            for (int q = 0; q < 4; q++) acc[mt][nt][q] = 0.f;

    const int brow = tid >> 4;
    const int bcol4 = (tid & 15) * 4;

    for (int k0 = 0; k0 < NTYPE * HD; k0 += 32) {
        __syncthreads();   // (first iter: orders gather writes; later: Bs reuse)
#pragma unroll
        for (int i2 = 0; i2 < 2; i2++) {
            int bk = brow + i2 * 16;
            float4 v = *reinterpret_cast<const float4*>(B + (size_t)(k0 + bk) * 64 + bcol4);
            *reinterpret_cast<float4*>(&Bs[bk * 72 + bcol4]) = v;
        }
        __syncthreads();
#pragma unroll
        for (int kk = 0; kk < 32; kk += 8) {
            unsigned a[2][4], b[4][2];
#pragma unroll
            for (int mt = 0; mt < 2; mt++) {
                int rb = warpRow * 32 + mt * 16;
                a[mt][0] = __float_as_uint(As[(rb + g)     * 324 + k0 + kk + tig]);
                a[mt][1] = __float_as_uint(As[(rb + g + 8) * 324 + k0 + kk + tig]);
                a[mt][2] = __float_as_uint(As[(rb + g)     * 324 + k0 + kk + tig + 4]);
                a[mt][3] = __float_as_uint(As[(rb + g + 8) * 324 + k0 + kk + tig + 4]);
            }
#pragma unroll
            for (int nt = 0; nt < 4; nt++) {
                int nb = warpCol * 32 + nt * 8 + g;
                b[nt][0] = __float_as_uint(Bs[(kk + tig)     * 72 + nb]);
                b[nt][1] = __float_as_uint(Bs[(kk + tig + 4) * 72 + nb]);
            }
#pragma unroll
            for (int mt = 0; mt < 2; mt++)
#pragma unroll
                for (int nt = 0; nt < 4; nt++)
                    mma_tf32(acc[mt][nt], a[mt], b[nt]);
        }
    }

    // ---- epilogue: relu(acc*deginv + bias) ----
#pragma unroll
    for (int mt = 0; mt < 2; mt++) {
        int r0 = rowBlk + warpRow * 32 + mt * 16 + g;
        int r1 = r0 + 8;
        float rs0 = (r0 < nrows) ? deginv[r0] : 1.f;
        float rs1 = (r1 < nrows) ? deginv[r1] : 1.f;
#pragma unroll
        for (int nt = 0; nt < 4; nt++) {
            int c = warpCol * 32 + nt * 8 + 2 * tig;
            float bv0 = bias[c], bv1 = bias[c + 1];
            if (r0 < nrows) {
                float v0 = fmaxf(acc[mt][nt][0] * rs0 + bv0, 0.f);
                float v1 = fmaxf(acc[mt][nt][1] * rs0 + bv1, 0.f);
                *reinterpret_cast<float2*>(Mout + (size_t)r0 * 64 + c) = make_float2(v0, v1);
            }
            if (r1 < nrows) {
                float v0 = fmaxf(acc[mt][nt][2] * rs1 + bv0, 0.f);
                float v1 = fmaxf(acc[mt][nt][3] * rs1 + bv1, 0.f);
                *reinterpret_cast<float2*>(Mout + (size_t)r1 * 64 + c) = make_float2(v0, v1);
            }
        }
    }
}

// ============================================================================
// K=64 GEMM, A staged once, NT sequential 64-col tiles. C = A@B + bias.
// dynamic smem: As[128*68] + Bs[64*72]  (~53 KB)
// ============================================================================
__global__ void __launch_bounds__(256)
gemm_k64_kernel(const float* __restrict__ A, const float* __restrict__ B,
                const float* __restrict__ bias, float* __restrict__ C,
                int nrows, int M, int NT) {
    extern __shared__ float smem[];
    float* As = smem;                 // [128][68]
    float* Bs = smem + 128 * 68;      // [64][72]
    const int tid = threadIdx.x;
    const int lane = tid & 31;
    const int wid = tid >> 5;
    const int warpRow = wid >> 1;
    const int warpCol = wid & 1;
    const int g = lane >> 2;
    const int tig = lane & 3;
    const int rowBlk = blockIdx.x * 128;

    // stage A (128 x 64)
    {
        const int arow = tid >> 1;
        const int aseg = (tid & 1) * 32;
        if (rowBlk + arow < nrows) {
#pragma unroll
            for (int i = 0; i < 8; i++)
                *reinterpret_cast<float4*>(&As[arow * 68 + aseg + i * 4]) =
                    *reinterpret_cast<const float4*>(A + (size_t)(rowBlk + arow) * 64 + aseg + i * 4);
        } else {
            float4 z = make_float4(0.f, 0.f, 0.f, 0.f);
#pragma unroll
            for (int i = 0; i < 8; i++)
                *reinterpret_cast<float4*>(&As[arow * 68 + aseg + i * 4]) = z;
        }
    }

    const int brow = tid >> 4;
    const int bcol4 = (tid & 15) * 4;

    for (int ct = 0; ct < NT; ct++) {
        __syncthreads();
#pragma unroll
        for (int i2 = 0; i2 < 4; i2++) {
            int bk = brow + i2 * 16;
            float4 v = *reinterpret_cast<const float4*>(B + (size_t)bk * M + ct * 64 + bcol4);
            *reinterpret_cast<float4*>(&Bs[bk * 72 + bcol4]) = v;
        }
        __syncthreads();

        float acc[2][4][4];
#pragma unroll
        for (int mt = 0; mt < 2; mt++)
#pragma unroll
            for (int nt = 0; nt < 4; nt++)
#pragma unroll
                for (int q = 0; q < 4; q++) acc[mt][nt][q] = 0.f;

#pragma unroll
        for (int kk = 0; kk < 64; kk += 8) {
            unsigned a[2][4], b[4][2];
#pragma unroll
            for (int mt = 0; mt < 2; mt++) {
                int rb = warpRow * 32 + mt * 16;
                a[mt][0] = __float_as_uint(As[(rb + g)     * 68 + kk + tig]);
                a[mt][1] = __float_as_uint(As[(rb + g + 8) * 68 + kk + tig]);
                a[mt][2] = __float_as_uint(As[(rb + g)     * 68 + kk + tig + 4]);
                a[mt][3] = __float_as_uint(As[(rb + g + 8) * 68 + kk + tig + 4]);
            }
#pragma unroll
            for (int nt = 0; nt < 4; nt++) {
                int nb = warpCol * 32 + nt * 8 + g;
                b[nt][0] = __float_as_uint(Bs[(kk + tig)     * 72 + nb]);
                b[nt][1] = __float_as_uint(Bs[(kk + tig + 4) * 72 + nb]);
            }
#pragma unroll
            for (int mt = 0; mt < 2; mt++)
#pragma unroll
                for (int nt = 0; nt < 4; nt++)
                    mma_tf32(acc[mt][nt], a[mt], b[nt]);
        }

#pragma unroll
        for (int mt = 0; mt < 2; mt++) {
            int r0 = rowBlk + warpRow * 32 + mt * 16 + g;
            int r1 = r0 + 8;
#pragma unroll
            for (int nt = 0; nt < 4; nt++) {
                int c = ct * 64 + warpCol * 32 + nt * 8 + 2 * tig;
                float bv0 = bias[c], bv1 = bias[c + 1];
                if (r0 < nrows)
                    *reinterpret_cast<float2*>(C + (size_t)r0 * M + c) =
                        make_float2(acc[mt][nt][0] + bv0, acc[mt][nt][1] + bv1);
                if (r1 < nrows)
                    *reinterpret_cast<float2*>(C + (size_t)r1 * M + c) =
                        make_float2(acc[mt][nt][2] + bv0, acc[mt][nt][3] + bv1);
            }
        }
    }
}

// ============================================================================
// Fused gh GEMM + GRU: gh = h @ w_hh (+b_hh); h' = GRU(gx, gh, h), in place.
// 3 col-tiles held in registers; h read from staged smem.
// dynamic smem: As[128*68] + Bs[64*72]
// ============================================================================
__global__ void __launch_bounds__(256)
gru_gemm_kernel(const float* __restrict__ Wh, const float* __restrict__ bhh,
                const float* __restrict__ gx, float* __restrict__ h, int nrows) {
    extern __shared__ float smem[];
    float* As = smem;
    float* Bs = smem + 128 * 68;
    const int tid = threadIdx.x;
    const int lane = tid & 31;
    const int wid = tid >> 5;
    const int warpRow = wid >> 1;
    const int warpCol = wid & 1;
    const int g = lane >> 2;
    const int tig = lane & 3;
    const int rowBlk = blockIdx.x * 128;

    // stage A = h (128 x 64)
    {
        const int arow = tid >> 1;
        const int aseg = (tid & 1) * 32;
        if (rowBlk + arow < nrows) {
#pragma unroll
            for (int i = 0; i < 8; i++)
                *reinterpret_cast<float4*>(&As[arow * 68 + aseg + i * 4]) =
                    *reinterpret_cast<const float4*>(h + (size_t)(rowBlk + arow) * 64 + aseg + i * 4);
        } else {
            float4 z = make_float4(0.f, 0.f, 0.f, 0.f);
#pragma unroll
            for (int i = 0; i < 8; i++)
                *reinterpret_cast<float4*>(&As[arow * 68 + aseg + i * 4]) = z;
        }
    }

    const int brow = tid >> 4;
    const int bcol4 = (tid & 15) * 4;

    float acc3[3][2][4][4];
#pragma unroll
    for (int ct = 0; ct < 3; ct++) {
        __syncthreads();
#pragma unroll
        for (int i2 = 0; i2 < 4; i2++) {
            int bk = brow + i2 * 16;
            float4 v = *reinterpret_cast<const float4*>(Wh + (size_t)bk * 192 + ct * 64 + bcol4);
            *reinterpret_cast<float4*>(&Bs[bk * 72 + bcol4]) = v;
        }
        __syncthreads();
#pragma unroll
        for (int mt = 0; mt < 2; mt++)
#pragma unroll
            for (int nt = 0; nt < 4; nt++)
#pragma unroll
                for (int q = 0; q < 4; q++) acc3[ct][mt][nt][q] = 0.f;

#pragma unroll
        for (int kk = 0; kk < 64; kk += 8) {
            unsigned a[2][4], b[4][2];
#pragma unroll
            for (int mt = 0; mt < 2; mt++) {
                int rb = warpRow * 32 + mt * 16;
                a[mt][0] = __float_as_uint(As[(rb + g)     * 68 + kk + tig]);
                a[mt][1] = __float_as_uint(As[(rb + g + 8) * 68 + kk + tig]);
                a[mt][2] = __float_as_uint(As[(rb + g)     * 68 + kk + tig + 4]);
                a[mt][3] = __float_as_uint(As[(rb + g + 8) * 68 + kk + tig + 4]);
            }
#pragma unroll
            for (int nt = 0; nt < 4; nt++) {
                int nb = warpCol * 32 + nt * 8 + g;
                b[nt][0] = __float_as_uint(Bs[(kk + tig)     * 72 + nb]);
                b[nt][1] = __float_as_uint(Bs[(kk + tig + 4) * 72 + nb]);
            }
#pragma unroll
            for (int mt = 0; mt < 2; mt++)
#pragma unroll
                for (int nt = 0; nt < 4; nt++)
                    mma_tf32(acc3[ct][mt][nt], a[mt], b[nt]);
        }
    }

    // ---- GRU epilogue ----
#pragma unroll
    for (int mt = 0; mt < 2; mt++) {
#pragma unroll
        for (int half = 0; half < 2; half++) {
            int lr = warpRow * 32 + mt * 16 + g + half * 8;
            int r = rowBlk + lr;
            if (r >= nrows) continue;
#pragma unroll
            for (int nt = 0; nt < 4; nt++) {
                int c = warpCol * 32 + nt * 8 + 2 * tig;
                int q = half * 2;
                float hr0 = acc3[0][mt][nt][q]     + bhh[c];
                float hr1 = acc3[0][mt][nt][q + 1] + bhh[c + 1];
                float hz0 = acc3[1][mt][nt][q]     + bhh[64 + c];
                float hz1 = acc3[1][mt][nt][q + 1] + bhh[64 + c + 1];
                float hn0 = acc3[2][mt][nt][q]     + bhh[128 + c];
                float hn1 = acc3[2][mt][nt][q + 1] + bhh[128 + c + 1];
                float2 gxr = *reinterpret_cast<const float2*>(gx + (size_t)r * 192 + c);
                float2 gxz = *reinterpret_cast<const float2*>(gx + (size_t)r * 192 + 64 + c);
                float2 gxn = *reinterpret_cast<const float2*>(gx + (size_t)r * 192 + 128 + c);
                float hv0 = As[lr * 68 + c];
                float hv1 = As[lr * 68 + c + 1];
                float rr0 = 1.f / (1.f + expf(-(gxr.x + hr0)));
                float rr1 = 1.f / (1.f + expf(-(gxr.y + hr1)));
                float zz0 = 1.f / (1.f + expf(-(gxz.x + hz0)));
                float zz1 = 1.f / (1.f + expf(-(gxz.y + hz1)));
                float nn0 = tanhf(gxn.x + rr0 * hn0);
                float nn1 = tanhf(gxn.y + rr1 * hn1);
                float o0 = (1.f - zz0) * nn0 + zz0 * hv0;
                float o1 = (1.f - zz1) * nn1 + zz1 * hv1;
                *reinterpret_cast<float2*>(h + (size_t)r * 64 + c) = make_float2(o0, o1);
            }
        }
    }
}

// ---------------- general tf32 GEMM (readout layers) ----------------
// EPI: 3 = sigmoid(+bias).  K % 32 == 0, M % 64 == 0.
template <int EPI, bool CONCAT>
__global__ void __launch_bounds__(256)
mma_gemm_kernel(const float* __restrict__ A, const float* __restrict__ A2,
                const float* __restrict__ B, const float* __restrict__ bias,
                float* __restrict__ C, int nrows, int K, int M) {
    __shared__ float As[128 * 36];
    __shared__ float Bs[32 * 72];
    const int tid = threadIdx.x;
    const int lane = tid & 31;
    const int wid = tid >> 5;
    const int warpRow = wid >> 1;
    const int warpCol = wid & 1;
    const int g = lane >> 2;
    const int tig = lane & 3;
    const int rowBlk = blockIdx.x * 128;
    const int colBlk = blockIdx.y * 64;

    float acc[2][4][4];
#pragma unroll
    for (int mt = 0; mt < 2; mt++)
#pragma unroll
        for (int nt = 0; nt < 4; nt++)
#pragma unroll
            for (int q = 0; q < 4; q++) acc[mt][nt][q] = 0.f;

    const int arow = tid >> 1;
    const int aseg = (tid & 1) * 16;
    const int brow = tid >> 4;
    const int bcol4 = (tid & 15) * 4;

    for (int k0 = 0; k0 < K; k0 += 32) {
        if (rowBlk + arow < nrows) {
#pragma unroll
            for (int i = 0; i < 4; i++) {
                int kk = k0 + aseg + i * 4;
                float4 v;
                if (CONCAT) {
                    const float* srcp = (kk < HD)
                        ? (A  + (size_t)(rowBlk + arow) * HD + kk)
                        : (A2 + (size_t)(rowBlk + arow) * HD + (kk - HD));
                    v = *reinterpret_cast<const float4*>(srcp);
                } else {
                    v = *reinterpret_cast<const float4*>(A + (size_t)(rowBlk + arow) * K + kk);
                }
                *reinterpret_cast<float4*>(&As[arow * 36 + aseg + i * 4]) = v;
            }
        } else {
            float4 z = make_float4(0.f, 0.f, 0.f, 0.f);
#pragma unroll
            for (int i = 0; i < 4; i++)
                *reinterpret_cast<float4*>(&As[arow * 36 + aseg + i * 4]) = z;
        }
#pragma unroll
        for (int i = 0; i < 2; i++) {
            int bk = brow + i * 16;
            float4 v = *reinterpret_cast<const float4*>(B + (size_t)(k0 + bk) * M + colBlk + bcol4);
            *reinterpret_cast<float4*>(&Bs[bk * 72 + bcol4]) = v;
        }
        __syncthreads();
#pragma unroll
        for (int kk = 0; kk < 32; kk += 8) {
            unsigned a[2][4], b[4][2];
#pragma unroll
            for (int mt = 0; mt < 2; mt++) {
                int rb = warpRow * 32 + mt * 16;
                a[mt][0] = __float_as_uint(As[(rb + g)     * 36 + kk + tig]);
                a[mt][1] = __float_as_uint(As[(rb + g + 8) * 36 + kk + tig]);
                a[mt][2] = __float_as_uint(As[(rb + g)     * 36 + kk + tig + 4]);
                a[mt][3] = __float_as_uint(As[(rb + g + 8) * 36 + kk + tig + 4]);
            }
#pragma unroll
            for (int nt = 0; nt < 4; nt++) {
                int nb = warpCol * 32 + nt * 8 + g;
                b[nt][0] = __float_as_uint(Bs[(kk + tig)     * 72 + nb]);
                b[nt][1] = __float_as_uint(Bs[(kk + tig + 4) * 72 + nb]);
            }
#pragma unroll
            for (int mt = 0; mt < 2; mt++)
#pragma unroll
                for (int nt = 0; nt < 4; nt++)
                    mma_tf32(acc[mt][nt], a[mt], b[nt]);
        }
        __syncthreads();
    }

#pragma unroll
    for (int mt = 0; mt < 2; mt++) {
        int r0 = rowBlk + warpRow * 32 + mt * 16 + g;
        int r1 = r0 + 8;
#pragma unroll
        for (int nt = 0; nt < 4; nt++) {
            int c = colBlk + warpCol * 32 + nt * 8 + 2 * tig;
            float bv0 = bias[c], bv1 = bias[c + 1];
            if (r0 < nrows) {
                float v0 = acc[mt][nt][0] + bv0, v1 = acc[mt][nt][1] + bv1;
                if (EPI == 3) { v0 = 1.f / (1.f + expf(-v0)); v1 = 1.f / (1.f + expf(-v1)); }
                *reinterpret_cast<float2*>(C + (size_t)r0 * M + c) = make_float2(v0, v1);
            }
            if (r1 < nrows) {
                float v0 = acc[mt][nt][2] + bv0, v1 = acc[mt][nt][3] + bv1;
                if (EPI == 3) { v0 = 1.f / (1.f + expf(-v0)); v1 = 1.f / (1.f + expf(-v1)); }
                *reinterpret_cast<float2*>(C + (size_t)r1 * M + c) = make_float2(v0, v1);
            }
        }
    }
}

// ---------------- fp32 FFMA GEMM for lin0 (K=15; double-write out0 and h) ----
__global__ void __launch_bounds__(256)
gemm_lin0_kernel(const float* __restrict__ A, const float* __restrict__ B,
                 const float* __restrict__ bias, float* __restrict__ C,
                 float* __restrict__ C2, int nrows, int K, int M) {
    __shared__ float As[128 * 17];
    __shared__ float Bs[16 * 64];
    const int tid = threadIdx.x;
    const int tx = tid & 15;
    const int ty = tid >> 4;
    const int rowBlk = blockIdx.x * 128;

    float acc[8][4];
#pragma unroll
    for (int i = 0; i < 8; i++)
#pragma unroll
        for (int j = 0; j < 4; j++) acc[i][j] = 0.f;

    const int m_ld = tid >> 1;
    const int kh = (tid & 1) * 8;
    const int grow = rowBlk + m_ld;

    for (int k0 = 0; k0 < K; k0 += 16) {
#pragma unroll
        for (int j = 0; j < 8; j++) {
            int kk = k0 + kh + j;
            float v = 0.f;
            if (grow < nrows && kk < K) v = A[(size_t)grow * K + kk];
            As[m_ld * 17 + kh + j] = v;
        }
        {
            int idx = tid * 4;
            int bk = idx >> 6;
            int bn = idx & 63;
#pragma unroll
            for (int j = 0; j < 4; j++) {
                int gk = k0 + bk;
                Bs[bk * 64 + bn + j] = (gk < K) ? __ldg(&B[gk * M + bn + j]) : 0.f;
            }
        }
        __syncthreads();
#pragma unroll
        for (int kk = 0; kk < 16; kk++) {
            float4 b4 = *reinterpret_cast<const float4*>(&Bs[kk * 64 + tx * 4]);
            float a[8];
#pragma unroll
            for (int i = 0; i < 8; i++) a[i] = As[(ty * 8 + i) * 17 + kk];
#pragma unroll
            for (int i = 0; i < 8; i++) {
                acc[i][0] += a[i] * b4.x;
                acc[i][1] += a[i] * b4.y;
                acc[i][2] += a[i] * b4.z;
                acc[i][3] += a[i] * b4.w;
            }
        }
        __syncthreads();
    }
#pragma unroll
    for (int i = 0; i < 8; i++) {
        int r = rowBlk + ty * 8 + i;
        if (r >= nrows) break;
#pragma unroll
        for (int j = 0; j < 4; j++) {
            int c = tx * 4 + j;
            float v = fmaxf(acc[i][j] + bias[c], 0.f);
            C[(size_t)r * M + c] = v;
            C2[(size_t)r * M + c] = v;
        }
    }
}

__global__ void zero_out_kernel(float* __restrict__ p) {
    int i = blockIdx.x * blockDim.x + threadIdx.x;
    if (i < NGRAPH * DOUT) p[i] = 0.f;
}

// ---------------- fused readout second layers + gating + graph pooling ----------------
__global__ void readout_kernel(const float* __restrict__ i1, const float* __restrict__ j1,
                               const float* __restrict__ iw2, const float* __restrict__ ib2,
                               const float* __restrict__ jw2, const float* __restrict__ jb2,
                               const int* __restrict__ batch, float* __restrict__ out) {
    __shared__ float swi[HD * DOUT], swj[HD * DOUT], sbi[DOUT], sbj[DOUT];
    int tid = threadIdx.x;
    for (int k = tid; k < HD * DOUT; k += blockDim.x) { swi[k] = iw2[k]; swj[k] = jw2[k]; }
    if (tid < DOUT) { sbi[tid] = ib2[tid]; sbj[tid] = jb2[tid]; }
    __syncthreads();
    int n = blockIdx.x * blockDim.x + tid;
    if (n >= NNODES) return;
    float ia[DOUT], ja[DOUT];
#pragma unroll
    for (int c = 0; c < DOUT; c++) { ia[c] = sbi[c]; ja[c] = sbj[c]; }
    const float* ir = i1 + (size_t)n * HD;
    const float* jr = j1 + (size_t)n * HD;
    for (int k = 0; k < HD; k++) {
        float a = ir[k], b = jr[k];
#pragma unroll
        for (int c = 0; c < DOUT; c++) {
            ia[c] += a * swi[k * DOUT + c];
            ja[c] += b * swj[k * DOUT + c];
        }
    }
    int g = batch[n] * DOUT;
#pragma unroll
    for (int c = 0; c < DOUT; c++) {
        float iv = 1.f / (1.f + expf(-ia[c]));
        atomicAdd(&out[g + c], iv * ja[c]);
    }
}

// ---------------- host launcher ----------------
extern "C" void kernel_launch(void* const* d_in, const int* in_sizes, int n_in,
                              void* d_out, int out_size) {
    const float* x      = (const float*)d_in[0];
    const int*   ei     = (const int*)d_in[1];
    const int*   src    = ei;
    const int*   dst    = ei + NEDGES;
    const int*   eattr  = (const int*)d_in[2];
    const int*   batch  = (const int*)d_in[3];
    const float* lin0_w = (const float*)d_in[4];
    const float* lin0_b = (const float*)d_in[5];
    const float* eembed = (const float*)d_in[6];   // [5,64,64] == B[320,64] row-major
    const float* conv_b = (const float*)d_in[7];
    const float* w_ih   = (const float*)d_in[8];
    const float* w_hh   = (const float*)d_in[9];
    const float* b_ih   = (const float*)d_in[10];
    const float* b_hh   = (const float*)d_in[11];
    const float* i_w1   = (const float*)d_in[12];
    const float* i_b1   = (const float*)d_in[13];
    const float* i_w2   = (const float*)d_in[14];
    const float* i_b2   = (const float*)d_in[15];
    const float* j_w1   = (const float*)d_in[16];
    const float* j_b1   = (const float*)d_in[17];
    const float* j_w2   = (const float*)d_in[18];
    const float* j_b2   = (const float*)d_in[19];
    float* out = (float*)d_out;

    float *p_out0, *p_h, *p_m, *p_i1, *p_j1, *p_gx, *p_deginv;
    cudaGetSymbolAddress((void**)&p_out0, g_out0);
    cudaGetSymbolAddress((void**)&p_h, g_h);
    cudaGetSymbolAddress((void**)&p_m, g_m);
    cudaGetSymbolAddress((void**)&p_i1, g_i1);
    cudaGetSymbolAddress((void**)&p_j1, g_j1);
    cudaGetSymbolAddress((void**)&p_gx, g_gx);
    cudaGetSymbolAddress((void**)&p_deginv, g_deginv);

    const int TB = 256;
    const int gN  = (NNODES + TB - 1) / TB;
    const int gE  = (NEDGES + TB - 1) / TB;
    const int RB  = (NNODES + 127) / 128;

    const int SMEM_NNCONV = (128 * 324 + 32 * 72) * 4;   // 175104
    const int SMEM_K64    = (128 * 68 + 64 * 72) * 4;    // 53248
    cudaFuncSetAttribute(nnconv_kernel, cudaFuncAttributeMaxDynamicSharedMemorySize, SMEM_NNCONV);
    cudaFuncSetAttribute(gemm_k64_kernel, cudaFuncAttributeMaxDynamicSharedMemorySize, SMEM_K64);
    cudaFuncSetAttribute(gru_gemm_kernel, cudaFuncAttributeMaxDynamicSharedMemorySize, SMEM_K64);

    // --- CSR build ---
    zero_cnt_kernel<<<gN, TB>>>();
    hist_kernel<<<gE, TB>>>(dst);
    scan1_kernel<<<NB, SCAN_B>>>();
    scan2_kernel<<<1, 128>>>();
    scan3_kernel<<<gN, TB>>>();
    scatter_kernel<<<gE, TB>>>(src, dst, eattr);

    // --- lin0: out0 = h = relu(x @ lin0_w + b) ---
    gemm_lin0_kernel<<<RB, TB>>>(x, lin0_w, lin0_b, p_out0, p_h, NNODES, DINP, HD);

    // --- propagation: fused agg+conv, gx GEMM, fused gh GEMM + GRU ---
    for (int step = 0; step < NSTEPS; step++) {
        nnconv_kernel<<<RB, TB, SMEM_NNCONV>>>((const float2*)p_h, eembed, conv_b,
                                               p_deginv, p_m, NNODES);
        gemm_k64_kernel<<<RB, TB, SMEM_K64>>>(p_m, w_ih, b_ih, p_gx, NNODES, 192, 3);
        gru_gemm_kernel<<<RB, TB, SMEM_K64>>>(w_hh, b_hh, p_gx, p_h, NNODES);
    }

    // --- readout ---
    mma_gemm_kernel<3, true><<<dim3(RB, 1), TB>>>(p_h, p_out0, i_w1, i_b1,
                                                  p_i1, NNODES, 2 * HD, HD);
    mma_gemm_kernel<3, false><<<dim3(RB, 1), TB>>>(p_h, nullptr, j_w1, j_b1,
                                                   p_j1, NNODES, HD, HD);
    zero_out_kernel<<<(NGRAPH * DOUT + TB - 1) / TB, TB>>>(out);
    readout_kernel<<<gN, TB>>>(p_i1, p_j1, i_w2, i_b2, j_w2, j_b2, batch, out);
}

// round 12
// speedup vs baseline: 2.1406x; 2.1406x over previous
#include <cuda_runtime.h>
#include <math.h>

#define NNODES 100000
#define NEDGES 3200000
#define HD 64
#define DINP 15
#define DOUT 12
#define NTYPE 5
#define NGRAPH 256
#define NSTEPS 6

#define SCAN_B 1024
#define NB ((NNODES + SCAN_B - 1) / SCAN_B)   // 98

// ---------------- scratch (device globals; no allocation) ----------------
__device__ float g_out0[NNODES * HD];
__device__ float g_h[NNODES * HD];
__device__ float g_m[NNODES * HD];
__device__ float g_i1[NNODES * HD];
__device__ float g_j1[NNODES * HD];
__device__ float g_agg[(size_t)NNODES * 320];
__device__ float g_gx[(size_t)NNODES * 192];
__device__ float g_deginv[NNODES];
__device__ int   g_rowptr[NNODES + 1];
__device__ int   g_cnt[NNODES];
__device__ int   g_cursor[NNODES];
__device__ int   g_bsums[128];
__device__ int   g_ecsr[NEDGES];

// ---------------- CSR build ----------------
__global__ void zero_cnt_kernel() {
    int i = blockIdx.x * blockDim.x + threadIdx.x;
    if (i < NNODES) g_cnt[i] = 0;
}

__global__ void hist_kernel(const int* __restrict__ dst) {
    int e = blockIdx.x * blockDim.x + threadIdx.x;
    if (e < NEDGES) atomicAdd(&g_cnt[dst[e]], 1);
}

__global__ void scan1_kernel() {
    __shared__ int s[SCAN_B];
    int tid = threadIdx.x;
    int g = blockIdx.x * SCAN_B + tid;
    int v = (g < NNODES) ? g_cnt[g] : 0;
    s[tid] = v;
    __syncthreads();
    for (int off = 1; off < SCAN_B; off <<= 1) {
        int t = (tid >= off) ? s[tid - off] : 0;
        __syncthreads();
        s[tid] += t;
        __syncthreads();
    }
    if (g < NNODES) g_rowptr[g] = s[tid] - v;
    if (tid == SCAN_B - 1) g_bsums[blockIdx.x] = s[tid];
}

__global__ void scan2_kernel() {
    __shared__ int s[128];
    int tid = threadIdx.x;
    int v = (tid < NB) ? g_bsums[tid] : 0;
    s[tid] = v;
    __syncthreads();
    for (int off = 1; off < 128; off <<= 1) {
        int t = (tid >= off) ? s[tid - off] : 0;
        __syncthreads();
        s[tid] += t;
        __syncthreads();
    }
    if (tid < NB) g_bsums[tid] = s[tid] - v;
    if (tid == 127) g_rowptr[NNODES] = s[127];
}

__global__ void scan3_kernel() {
    int g = blockIdx.x * blockDim.x + threadIdx.x;
    if (g >= NNODES) return;
    g_rowptr[g] += g_bsums[g >> 10];
    g_cursor[g] = 0;
    int d = g_cnt[g];
    g_deginv[g] = 1.0f / (float)(d > 0 ? d : 1);
}

__global__ void scatter_kernel(const int* __restrict__ src,
                               const int* __restrict__ dst,
                               const int* __restrict__ typ) {
    int e = blockIdx.x * blockDim.x + threadIdx.x;
    if (e >= NEDGES) return;
    int d = dst[e];
    int pos = atomicAdd(&g_cursor[d], 1);
    g_ecsr[g_rowptr[d] + pos] = src[e] | (typ[e] << 17);  // N < 2^17
}

// ---------------- tf32 mma helper ----------------
__device__ __forceinline__ void mma_tf32(float* d, const unsigned* a, const unsigned* b) {
    asm volatile(
        "mma.sync.aligned.m16n8k8.row.col.f32.tf32.tf32.f32 "
        "{%0,%1,%2,%3}, {%4,%5,%6,%7}, {%8,%9}, {%0,%1,%2,%3};\n"
        : "+f"(d[0]), "+f"(d[1]), "+f"(d[2]), "+f"(d[3])
        : "r"(a[0]), "r"(a[1]), "r"(a[2]), "r"(a[3]), "r"(b[0]), "r"(b[1]));
}

// ---------------- per-type neighbor aggregation (warp per node, full occupancy) ----
__global__ void agg_kernel(const float2* __restrict__ out2, float2* __restrict__ agg2) {
    int w = (blockIdx.x * blockDim.x + threadIdx.x) >> 5;
    int lane = threadIdx.x & 31;
    if (w >= NNODES) return;
    int s = g_rowptr[w];
    int e = g_rowptr[w + 1];
    float2 acc[NTYPE];
#pragma unroll
    for (int t = 0; t < NTYPE; t++) { acc[t].x = 0.f; acc[t].y = 0.f; }
    int i = s;
    for (; i + 1 < e; i += 2) {
        int e0 = __ldg(&g_ecsr[i]);
        int e1 = __ldg(&g_ecsr[i + 1]);
        float2 v0 = out2[(e0 & 0x1FFFF) * 32 + lane];
        float2 v1 = out2[(e1 & 0x1FFFF) * 32 + lane];
        int t0 = e0 >> 17, t1 = e1 >> 17;
#pragma unroll
        for (int t = 0; t < NTYPE; t++) {
            if (t0 == t) { acc[t].x += v0.x; acc[t].y += v0.y; }
            if (t1 == t) { acc[t].x += v1.x; acc[t].y += v1.y; }
        }
    }
    if (i < e) {
        int e0 = __ldg(&g_ecsr[i]);
        float2 v0 = out2[(e0 & 0x1FFFF) * 32 + lane];
        int t0 = e0 >> 17;
#pragma unroll
        for (int t = 0; t < NTYPE; t++)
            if (t0 == t) { acc[t].x += v0.x; acc[t].y += v0.y; }
    }
    size_t base = (size_t)w * (NTYPE * 32);
#pragma unroll
    for (int t = 0; t < NTYPE; t++) agg2[base + t * 32 + lane] = acc[t];
}

// ---------------- general tf32 GEMM ----------------
// EPI: 0 = +bias; 2 = relu(acc*rowscale + bias); 3 = sigmoid(+bias)
template <int EPI, bool CONCAT>
__global__ void __launch_bounds__(256)
mma_gemm_kernel(const float* __restrict__ A, const float* __restrict__ A2,
                const float* __restrict__ B, const float* __restrict__ bias,
                const float* __restrict__ rowscale, float* __restrict__ C,
                int nrows, int K, int M) {
    __shared__ float As[128 * 36];
    __shared__ float Bs[32 * 72];
    const int tid = threadIdx.x;
    const int lane = tid & 31;
    const int wid = tid >> 5;
    const int warpRow = wid >> 1;
    const int warpCol = wid & 1;
    const int g = lane >> 2;
    const int tig = lane & 3;
    const int rowBlk = blockIdx.x * 128;
    const int colBlk = blockIdx.y * 64;

    float acc[2][4][4];
#pragma unroll
    for (int mt = 0; mt < 2; mt++)
#pragma unroll
        for (int nt = 0; nt < 4; nt++)
#pragma unroll
            for (int q = 0; q < 4; q++) acc[mt][nt][q] = 0.f;

    const int arow = tid >> 1;
    const int aseg = (tid & 1) * 16;
    const int brow = tid >> 4;
    const int bcol4 = (tid & 15) * 4;

    for (int k0 = 0; k0 < K; k0 += 32) {
        if (rowBlk + arow < nrows) {
#pragma unroll
            for (int i = 0; i < 4; i++) {
                int kk = k0 + aseg + i * 4;
                float4 v;
                if (CONCAT) {
                    const float* srcp = (kk < HD)
                        ? (A  + (size_t)(rowBlk + arow) * HD + kk)
                        : (A2 + (size_t)(rowBlk + arow) * HD + (kk - HD));
                    v = *reinterpret_cast<const float4*>(srcp);
                } else {
                    v = *reinterpret_cast<const float4*>(A + (size_t)(rowBlk + arow) * K + kk);
                }
                *reinterpret_cast<float4*>(&As[arow * 36 + aseg + i * 4]) = v;
            }
        } else {
            float4 z = make_float4(0.f, 0.f, 0.f, 0.f);
#pragma unroll
            for (int i = 0; i < 4; i++)
                *reinterpret_cast<float4*>(&As[arow * 36 + aseg + i * 4]) = z;
        }
#pragma unroll
        for (int i = 0; i < 2; i++) {
            int bk = brow + i * 16;
            float4 v = *reinterpret_cast<const float4*>(B + (size_t)(k0 + bk) * M + colBlk + bcol4);
            *reinterpret_cast<float4*>(&Bs[bk * 72 + bcol4]) = v;
        }
        __syncthreads();
#pragma unroll
        for (int kk = 0; kk < 32; kk += 8) {
            unsigned a[2][4], b[4][2];
#pragma unroll
            for (int mt = 0; mt < 2; mt++) {
                int rb = warpRow * 32 + mt * 16;
                a[mt][0] = __float_as_uint(As[(rb + g)     * 36 + kk + tig]);
                a[mt][1] = __float_as_uint(As[(rb + g + 8) * 36 + kk + tig]);
                a[mt][2] = __float_as_uint(As[(rb + g)     * 36 + kk + tig + 4]);
                a[mt][3] = __float_as_uint(As[(rb + g + 8) * 36 + kk + tig + 4]);
            }
#pragma unroll
            for (int nt = 0; nt < 4; nt++) {
                int nb = warpCol * 32 + nt * 8 + g;
                b[nt][0] = __float_as_uint(Bs[(kk + tig)     * 72 + nb]);
                b[nt][1] = __float_as_uint(Bs[(kk + tig + 4) * 72 + nb]);
            }
#pragma unroll
            for (int mt = 0; mt < 2; mt++)
#pragma unroll
                for (int nt = 0; nt < 4; nt++)
                    mma_tf32(acc[mt][nt], a[mt], b[nt]);
        }
        __syncthreads();
    }

#pragma unroll
    for (int mt = 0; mt < 2; mt++) {
        int r0 = rowBlk + warpRow * 32 + mt * 16 + g;
        int r1 = r0 + 8;
        float rs0 = 1.f, rs1 = 1.f;
        if (EPI == 2) {
            if (r0 < nrows) rs0 = rowscale[r0];
            if (r1 < nrows) rs1 = rowscale[r1];
        }
#pragma unroll
        for (int nt = 0; nt < 4; nt++) {
            int c = colBlk + warpCol * 32 + nt * 8 + 2 * tig;
            float bv0 = bias[c], bv1 = bias[c + 1];
            if (r0 < nrows) {
                float v0 = acc[mt][nt][0], v1 = acc[mt][nt][1];
                if (EPI == 2) { v0 *= rs0; v1 *= rs0; }
                v0 += bv0; v1 += bv1;
                if (EPI == 2) { v0 = fmaxf(v0, 0.f); v1 = fmaxf(v1, 0.f); }
                if (EPI == 3) { v0 = 1.f / (1.f + expf(-v0)); v1 = 1.f / (1.f + expf(-v1)); }
                *reinterpret_cast<float2*>(C + (size_t)r0 * M + c) = make_float2(v0, v1);
            }
            if (r1 < nrows) {
                float v0 = acc[mt][nt][2], v1 = acc[mt][nt][3];
                if (EPI == 2) { v0 *= rs1; v1 *= rs1; }
                v0 += bv0; v1 += bv1;
                if (EPI == 2) { v0 = fmaxf(v0, 0.f); v1 = fmaxf(v1, 0.f); }
                if (EPI == 3) { v0 = 1.f / (1.f + expf(-v0)); v1 = 1.f / (1.f + expf(-v1)); }
                *reinterpret_cast<float2*>(C + (size_t)r1 * M + c) = make_float2(v0, v1);
            }
        }
    }
}

// ============================================================================
// K=64 GEMM, A staged once, NT sequential 64-col tiles. C = A@B + bias.
// dynamic smem: As[128*68] + Bs[64*72]  (~53 KB -> 4 blocks/SM)
// ============================================================================
__global__ void __launch_bounds__(256)
gemm_k64_kernel(const float* __restrict__ A, const float* __restrict__ B,
                const float* __restrict__ bias, float* __restrict__ C,
                int nrows, int M, int NT) {
    extern __shared__ float smem[];
    float* As = smem;                 // [128][68]
    float* Bs = smem + 128 * 68;      // [64][72]
    const int tid = threadIdx.x;
    const int lane = tid & 31;
    const int wid = tid >> 5;
    const int warpRow = wid >> 1;
    const int warpCol = wid & 1;
    const int g = lane >> 2;
    const int tig = lane & 3;
    const int rowBlk = blockIdx.x * 128;

    {
        const int arow = tid >> 1;
        const int aseg = (tid & 1) * 32;
        if (rowBlk + arow < nrows) {
#pragma unroll
            for (int i = 0; i < 8; i++)
                *reinterpret_cast<float4*>(&As[arow * 68 + aseg + i * 4]) =
                    *reinterpret_cast<const float4*>(A + (size_t)(rowBlk + arow) * 64 + aseg + i * 4);
        } else {
            float4 z = make_float4(0.f, 0.f, 0.f, 0.f);
#pragma unroll
            for (int i = 0; i < 8; i++)
                *reinterpret_cast<float4*>(&As[arow * 68 + aseg + i * 4]) = z;
        }
    }

    const int brow = tid >> 4;
    const int bcol4 = (tid & 15) * 4;

    for (int ct = 0; ct < NT; ct++) {
        __syncthreads();
#pragma unroll
        for (int i2 = 0; i2 < 4; i2++) {
            int bk = brow + i2 * 16;
            float4 v = *reinterpret_cast<const float4*>(B + (size_t)bk * M + ct * 64 + bcol4);
            *reinterpret_cast<float4*>(&Bs[bk * 72 + bcol4]) = v;
        }
        __syncthreads();

        float acc[2][4][4];
#pragma unroll
        for (int mt = 0; mt < 2; mt++)
#pragma unroll
            for (int nt = 0; nt < 4; nt++)
#pragma unroll
                for (int q = 0; q < 4; q++) acc[mt][nt][q] = 0.f;

#pragma unroll
        for (int kk = 0; kk < 64; kk += 8) {
            unsigned a[2][4], b[4][2];
#pragma unroll
            for (int mt = 0; mt < 2; mt++) {
                int rb = warpRow * 32 + mt * 16;
                a[mt][0] = __float_as_uint(As[(rb + g)     * 68 + kk + tig]);
                a[mt][1] = __float_as_uint(As[(rb + g + 8) * 68 + kk + tig]);
                a[mt][2] = __float_as_uint(As[(rb + g)     * 68 + kk + tig + 4]);
                a[mt][3] = __float_as_uint(As[(rb + g + 8) * 68 + kk + tig + 4]);
            }
#pragma unroll
            for (int nt = 0; nt < 4; nt++) {
                int nb = warpCol * 32 + nt * 8 + g;
                b[nt][0] = __float_as_uint(Bs[(kk + tig)     * 72 + nb]);
                b[nt][1] = __float_as_uint(Bs[(kk + tig + 4) * 72 + nb]);
            }
#pragma unroll
            for (int mt = 0; mt < 2; mt++)
#pragma unroll
                for (int nt = 0; nt < 4; nt++)
                    mma_tf32(acc[mt][nt], a[mt], b[nt]);
        }

#pragma unroll
        for (int mt = 0; mt < 2; mt++) {
            int r0 = rowBlk + warpRow * 32 + mt * 16 + g;
            int r1 = r0 + 8;
#pragma unroll
            for (int nt = 0; nt < 4; nt++) {
                int c = ct * 64 + warpCol * 32 + nt * 8 + 2 * tig;
                float bv0 = bias[c], bv1 = bias[c + 1];
                if (r0 < nrows)
                    *reinterpret_cast<float2*>(C + (size_t)r0 * M + c) =
                        make_float2(acc[mt][nt][0] + bv0, acc[mt][nt][1] + bv1);
                if (r1 < nrows)
                    *reinterpret_cast<float2*>(C + (size_t)r1 * M + c) =
                        make_float2(acc[mt][nt][2] + bv0, acc[mt][nt][3] + bv1);
            }
        }
    }
}

// ============================================================================
// Fused gh GEMM + GRU: gh = h @ w_hh (+b_hh); h' = GRU(gx, gh, h), in place.
// ============================================================================
__global__ void __launch_bounds__(256)
gru_gemm_kernel(const float* __restrict__ Wh, const float* __restrict__ bhh,
                const float* __restrict__ gx, float* __restrict__ h, int nrows) {
    extern __shared__ float smem[];
    float* As = smem;
    float* Bs = smem + 128 * 68;
    const int tid = threadIdx.x;
    const int lane = tid & 31;
    const int wid = tid >> 5;
    const int warpRow = wid >> 1;
    const int warpCol = wid & 1;
    const int g = lane >> 2;
    const int tig = lane & 3;
    const int rowBlk = blockIdx.x * 128;

    {
        const int arow = tid >> 1;
        const int aseg = (tid & 1) * 32;
        if (rowBlk + arow < nrows) {
#pragma unroll
            for (int i = 0; i < 8; i++)
                *reinterpret_cast<float4*>(&As[arow * 68 + aseg + i * 4]) =
                    *reinterpret_cast<const float4*>(h + (size_t)(rowBlk + arow) * 64 + aseg + i * 4);
        } else {
            float4 z = make_float4(0.f, 0.f, 0.f, 0.f);
#pragma unroll
            for (int i = 0; i < 8; i++)
                *reinterpret_cast<float4*>(&As[arow * 68 + aseg + i * 4]) = z;
        }
    }

    const int brow = tid >> 4;
    const int bcol4 = (tid & 15) * 4;

    float acc3[3][2][4][4];
#pragma unroll
    for (int ct = 0; ct < 3; ct++) {
        __syncthreads();
#pragma unroll
        for (int i2 = 0; i2 < 4; i2++) {
            int bk = brow + i2 * 16;
            float4 v = *reinterpret_cast<const float4*>(Wh + (size_t)bk * 192 + ct * 64 + bcol4);
            *reinterpret_cast<float4*>(&Bs[bk * 72 + bcol4]) = v;
        }
        __syncthreads();
#pragma unroll
        for (int mt = 0; mt < 2; mt++)
#pragma unroll
            for (int nt = 0; nt < 4; nt++)
#pragma unroll
                for (int q = 0; q < 4; q++) acc3[ct][mt][nt][q] = 0.f;

#pragma unroll
        for (int kk = 0; kk < 64; kk += 8) {
            unsigned a[2][4], b[4][2];
#pragma unroll
            for (int mt = 0; mt < 2; mt++) {
                int rb = warpRow * 32 + mt * 16;
                a[mt][0] = __float_as_uint(As[(rb + g)     * 68 + kk + tig]);
                a[mt][1] = __float_as_uint(As[(rb + g + 8) * 68 + kk + tig]);
                a[mt][2] = __float_as_uint(As[(rb + g)     * 68 + kk + tig + 4]);
                a[mt][3] = __float_as_uint(As[(rb + g + 8) * 68 + kk + tig + 4]);
            }
#pragma unroll
            for (int nt = 0; nt < 4; nt++) {
                int nb = warpCol * 32 + nt * 8 + g;
                b[nt][0] = __float_as_uint(Bs[(kk + tig)     * 72 + nb]);
                b[nt][1] = __float_as_uint(Bs[(kk + tig + 4) * 72 + nb]);
            }
#pragma unroll
            for (int mt = 0; mt < 2; mt++)
#pragma unroll
                for (int nt = 0; nt < 4; nt++)
                    mma_tf32(acc3[ct][mt][nt], a[mt], b[nt]);
        }
    }

    // ---- GRU epilogue ----
#pragma unroll
    for (int mt = 0; mt < 2; mt++) {
#pragma unroll
        for (int half = 0; half < 2; half++) {
            int lr = warpRow * 32 + mt * 16 + g + half * 8;
            int r = rowBlk + lr;
            if (r >= nrows) continue;
#pragma unroll
            for (int nt = 0; nt < 4; nt++) {
                int c = warpCol * 32 + nt * 8 + 2 * tig;
                int q = half * 2;
                float hr0 = acc3[0][mt][nt][q]     + bhh[c];
                float hr1 = acc3[0][mt][nt][q + 1] + bhh[c + 1];
                float hz0 = acc3[1][mt][nt][q]     + bhh[64 + c];
                float hz1 = acc3[1][mt][nt][q + 1] + bhh[64 + c + 1];
                float hn0 = acc3[2][mt][nt][q]     + bhh[128 + c];
                float hn1 = acc3[2][mt][nt][q + 1] + bhh[128 + c + 1];
                float2 gxr = *reinterpret_cast<const float2*>(gx + (size_t)r * 192 + c);
                float2 gxz = *reinterpret_cast<const float2*>(gx + (size_t)r * 192 + 64 + c);
                float2 gxn = *reinterpret_cast<const float2*>(gx + (size_t)r * 192 + 128 + c);
                float hv0 = As[lr * 68 + c];
                float hv1 = As[lr * 68 + c + 1];
                float rr0 = 1.f / (1.f + expf(-(gxr.x + hr0)));
                float rr1 = 1.f / (1.f + expf(-(gxr.y + hr1)));
                float zz0 = 1.f / (1.f + expf(-(gxz.x + hz0)));
                float zz1 = 1.f / (1.f + expf(-(gxz.y + hz1)));
                float nn0 = tanhf(gxn.x + rr0 * hn0);
                float nn1 = tanhf(gxn.y + rr1 * hn1);
                float o0 = (1.f - zz0) * nn0 + zz0 * hv0;
                float o1 = (1.f - zz1) * nn1 + zz1 * hv1;
                *reinterpret_cast<float2*>(h + (size_t)r * 64 + c) = make_float2(o0, o1);
            }
        }
    }
}

// ---------------- fp32 FFMA GEMM for lin0 (K=15; double-write out0 and h) ----
__global__ void __launch_bounds__(256)
gemm_lin0_kernel(const float* __restrict__ A, const float* __restrict__ B,
                 const float* __restrict__ bias, float* __restrict__ C,
                 float* __restrict__ C2, int nrows, int K, int M) {
    __shared__ float As[128 * 17];
    __shared__ float Bs[16 * 64];
    const int tid = threadIdx.x;
    const int tx = tid & 15;
    const int ty = tid >> 4;
    const int rowBlk = blockIdx.x * 128;

    float acc[8][4];
#pragma unroll
    for (int i = 0; i < 8; i++)
#pragma unroll
        for (int j = 0; j < 4; j++) acc[i][j] = 0.f;

    const int m_ld = tid >> 1;
    const int kh = (tid & 1) * 8;
    const int grow = rowBlk + m_ld;

    for (int k0 = 0; k0 < K; k0 += 16) {
#pragma unroll
        for (int j = 0; j < 8; j++) {
            int kk = k0 + kh + j;
            float v = 0.f;
            if (grow < nrows && kk < K) v = A[(size_t)grow * K + kk];
            As[m_ld * 17 + kh + j] = v;
        }
        {
            int idx = tid * 4;
            int bk = idx >> 6;
            int bn = idx & 63;
#pragma unroll
            for (int j = 0; j < 4; j++) {
                int gk = k0 + bk;
                Bs[bk * 64 + bn + j] = (gk < K) ? __ldg(&B[gk * M + bn + j]) : 0.f;
            }
        }
        __syncthreads();
#pragma unroll
        for (int kk = 0; kk < 16; kk++) {
            float4 b4 = *reinterpret_cast<const float4*>(&Bs[kk * 64 + tx * 4]);
            float a[8];
#pragma unroll
            for (int i = 0; i < 8; i++) a[i] = As[(ty * 8 + i) * 17 + kk];
#pragma unroll
            for (int i = 0; i < 8; i++) {
                acc[i][0] += a[i] * b4.x;
                acc[i][1] += a[i] * b4.y;
                acc[i][2] += a[i] * b4.z;
                acc[i][3] += a[i] * b4.w;
            }
        }
        __syncthreads();
    }
#pragma unroll
    for (int i = 0; i < 8; i++) {
        int r = rowBlk + ty * 8 + i;
        if (r >= nrows) break;
#pragma unroll
        for (int j = 0; j < 4; j++) {
            int c = tx * 4 + j;
            float v = fmaxf(acc[i][j] + bias[c], 0.f);
            C[(size_t)r * M + c] = v;
            C2[(size_t)r * M + c] = v;
        }
    }
}

__global__ void zero_out_kernel(float* __restrict__ p) {
    int i = blockIdx.x * blockDim.x + threadIdx.x;
    if (i < NGRAPH * DOUT) p[i] = 0.f;
}

// ---------------- fused readout second layers + gating + graph pooling ----------------
__global__ void readout_kernel(const float* __restrict__ i1, const float* __restrict__ j1,
                               const float* __restrict__ iw2, const float* __restrict__ ib2,
                               const float* __restrict__ jw2, const float* __restrict__ jb2,
                               const int* __restrict__ batch, float* __restrict__ out) {
    __shared__ float swi[HD * DOUT], swj[HD * DOUT], sbi[DOUT], sbj[DOUT];
    int tid = threadIdx.x;
    for (int k = tid; k < HD * DOUT; k += blockDim.x) { swi[k] = iw2[k]; swj[k] = jw2[k]; }
    if (tid < DOUT) { sbi[tid] = ib2[tid]; sbj[tid] = jb2[tid]; }
    __syncthreads();
    int n = blockIdx.x * blockDim.x + tid;
    if (n >= NNODES) return;
    float ia[DOUT], ja[DOUT];
#pragma unroll
    for (int c = 0; c < DOUT; c++) { ia[c] = sbi[c]; ja[c] = sbj[c]; }
    const float* ir = i1 + (size_t)n * HD;
    const float* jr = j1 + (size_t)n * HD;
    for (int k = 0; k < HD; k++) {
        float a = ir[k], b = jr[k];
#pragma unroll
        for (int c = 0; c < DOUT; c++) {
            ia[c] += a * swi[k * DOUT + c];
            ja[c] += b * swj[k * DOUT + c];
        }
    }
    int g = batch[n] * DOUT;
#pragma unroll
    for (int c = 0; c < DOUT; c++) {
        float iv = 1.f / (1.f + expf(-ia[c]));
        atomicAdd(&out[g + c], iv * ja[c]);
    }
}

// ---------------- host launcher ----------------
extern "C" void kernel_launch(void* const* d_in, const int* in_sizes, int n_in,
                              void* d_out, int out_size) {
    const float* x      = (const float*)d_in[0];
    const int*   ei     = (const int*)d_in[1];
    const int*   src    = ei;
    const int*   dst    = ei + NEDGES;
    const int*   eattr  = (const int*)d_in[2];
    const int*   batch  = (const int*)d_in[3];
    const float* lin0_w = (const float*)d_in[4];
    const float* lin0_b = (const float*)d_in[5];
    const float* eembed = (const float*)d_in[6];   // [5,64,64] == B[320,64] row-major
    const float* conv_b = (const float*)d_in[7];
    const float* w_ih   = (const float*)d_in[8];
    const float* w_hh   = (const float*)d_in[9];
    const float* b_ih   = (const float*)d_in[10];
    const float* b_hh   = (const float*)d_in[11];
    const float* i_w1   = (const float*)d_in[12];
    const float* i_b1   = (const float*)d_in[13];
    const float* i_w2   = (const float*)d_in[14];
    const float* i_b2   = (const float*)d_in[15];
    const float* j_w1   = (const float*)d_in[16];
    const float* j_b1   = (const float*)d_in[17];
    const float* j_w2   = (const float*)d_in[18];
    const float* j_b2   = (const float*)d_in[19];
    float* out = (float*)d_out;

    float *p_out0, *p_h, *p_m, *p_i1, *p_j1, *p_agg, *p_gx, *p_deginv;
    cudaGetSymbolAddress((void**)&p_out0, g_out0);
    cudaGetSymbolAddress((void**)&p_h, g_h);
    cudaGetSymbolAddress((void**)&p_m, g_m);
    cudaGetSymbolAddress((void**)&p_i1, g_i1);
    cudaGetSymbolAddress((void**)&p_j1, g_j1);
    cudaGetSymbolAddress((void**)&p_agg, g_agg);
    cudaGetSymbolAddress((void**)&p_gx, g_gx);
    cudaGetSymbolAddress((void**)&p_deginv, g_deginv);

    const int TB = 256;
    const int gN  = (NNODES + TB - 1) / TB;
    const int gE  = (NEDGES + TB - 1) / TB;
    const int gW  = (NNODES * 32 + TB - 1) / TB;       // warp-per-node
    const int RB  = (NNODES + 127) / 128;

    const int SMEM_K64 = (128 * 68 + 64 * 72) * 4;     // 53248
    cudaFuncSetAttribute(gemm_k64_kernel, cudaFuncAttributeMaxDynamicSharedMemorySize, SMEM_K64);
    cudaFuncSetAttribute(gru_gemm_kernel, cudaFuncAttributeMaxDynamicSharedMemorySize, SMEM_K64);

    // --- CSR build ---
    zero_cnt_kernel<<<gN, TB>>>();
    hist_kernel<<<gE, TB>>>(dst);
    scan1_kernel<<<NB, SCAN_B>>>();
    scan2_kernel<<<1, 128>>>();
    scan3_kernel<<<gN, TB>>>();
    scatter_kernel<<<gE, TB>>>(src, dst, eattr);

    // --- lin0: out0 = h = relu(x @ lin0_w + b) ---
    gemm_lin0_kernel<<<RB, TB>>>(x, lin0_w, lin0_b, p_out0, p_h, NNODES, DINP, HD);

    // --- propagation: high-occupancy agg, conv GEMM, gx GEMM, fused gh+GRU ---
    for (int step = 0; step < NSTEPS; step++) {
        agg_kernel<<<gW, TB>>>((const float2*)p_h, (float2*)p_agg);
        mma_gemm_kernel<2, false><<<dim3(RB, 1), TB>>>(p_agg, nullptr, eembed, conv_b,
                                                       p_deginv, p_m, NNODES, NTYPE * HD, HD);
        gemm_k64_kernel<<<RB, TB, SMEM_K64>>>(p_m, w_ih, b_ih, p_gx, NNODES, 192, 3);
        gru_gemm_kernel<<<RB, TB, SMEM_K64>>>(w_hh, b_hh, p_gx, p_h, NNODES);
    }

    // --- readout ---
    mma_gemm_kernel<3, true><<<dim3(RB, 1), TB>>>(p_h, p_out0, i_w1, i_b1, nullptr,
                                                  p_i1, NNODES, 2 * HD, HD);
    mma_gemm_kernel<3, false><<<dim3(RB, 1), TB>>>(p_h, nullptr, j_w1, j_b1, nullptr,
                                                   p_j1, NNODES, HD, HD);
    zero_out_kernel<<<(NGRAPH * DOUT + TB - 1) / TB, TB>>>(out);
    readout_kernel<<<gN, TB>>>(p_i1, p_j1, i_w2, i_b2, j_w2, j_b2, batch, out);
}